// round 2
// baseline (speedup 1.0000x reference)
#include <cuda_runtime.h>

#define NB 8
#define OP 400
#define MA 200
#define F 64

// Scratch (allocation-free rule: __device__ globals)
__device__ float g_hop[NB*OP*F];   // h_op = x @ W_op
__device__ float g_sop[NB*OP];     // h_op . a_op
__device__ float g_h  [NB*MA*F];   // h = y @ W_ma
__device__ float g_sma[NB*MA];     // h . a_ma
__device__ float g_vedge[F];       // W_edge @ a_edge

// ---------------------------------------------------------------------------
// Prep kernel: small GEMVs.
// blocks [0, NB*OP)         : row of x  -> g_hop, g_sop
// blocks [NB*OP, NB*OP+NB*MA): row of y -> g_h, g_sma
// block  NB*OP+NB*MA        : v_edge
// ---------------------------------------------------------------------------
__global__ void prep_kernel(const float* __restrict__ x, const float* __restrict__ y,
                            const float* __restrict__ Wop, const float* __restrict__ Wma,
                            const float* __restrict__ Wedge, const float* __restrict__ att)
{
    int blk = blockIdx.x;
    int t = threadIdx.x;

    if (blk == NB*OP + NB*MA) {
        float acc = 0.f;
        #pragma unroll
        for (int f = 0; f < F; f++) acc += Wedge[t*F + f] * att[2*F + f];
        g_vedge[t] = acc;
        return;
    }

    const float* in; const float* W; const float* a;
    float* hout; float* sout;
    if (blk < NB*OP) {
        int row = blk;
        in = x + row*F; W = Wop; a = att;
        hout = g_hop + row*F; sout = g_sop + row;
    } else {
        int row = blk - NB*OP;
        in = y + row*F; W = Wma; a = att + F;
        hout = g_h + row*F; sout = g_sma + row;
    }

    __shared__ float srow[F];
    __shared__ float sred[2];
    srow[t] = in[t];
    __syncthreads();

    float acc = 0.f;
    #pragma unroll
    for (int i = 0; i < F; i++) acc += srow[i] * W[i*F + t];
    hout[t] = acc;

    float v = acc * a[t];
    #pragma unroll
    for (int o = 16; o; o >>= 1) v += __shfl_xor_sync(0xffffffffu, v, o);
    if ((t & 31) == 0) sred[t >> 5] = v;
    __syncthreads();
    if (t == 0) sout[0] = sred[0] + sred[1];
}

// ---------------------------------------------------------------------------
// Main kernel: one CTA per (b, m). 4 warps split n; each warp covers all 64 f
// (float2 per lane). Single pass over z, masked-skip, softmax without max
// subtraction (|e| is small by construction), epilogue applies W_edge to the
// attention-weighted z sum.
// ---------------------------------------------------------------------------
__global__ __launch_bounds__(128) void edge_gat_kernel(
    const float*  __restrict__ z,
    const int*    __restrict__ adj,
    const float*  __restrict__ Wedge,
    float*        __restrict__ out)
{
    const int bid = blockIdx.x;
    const int b = bid / MA;
    const int m = bid % MA;
    const int tid = threadIdx.x;
    const int w = tid >> 5;
    const int lane = tid & 31;

    __shared__ float s_sop[OP];
    __shared__ int   s_mask[OP];
    __shared__ float s_pz[4*F];
    __shared__ float s_ph[4*F];
    __shared__ float s_pd[4];
    __shared__ float s_accz[F];

    for (int i = tid; i < OP; i += 128) {
        s_sop[i]  = g_sop[b*OP + i];
        s_mask[i] = adj[(b*OP + i)*MA + m];   // adjT[b,m,i]
    }
    const float  sma = g_sma[b*MA + m];
    const float2 ve  = ((const float2*)g_vedge)[lane];
    __syncthreads();

    float2 accz = make_float2(0.f, 0.f);
    float2 acch = make_float2(0.f, 0.f);
    float  denom = 0.f;

    const float2* zb = (const float2*)z;
    const float2* hb = (const float2*)g_hop;

    // warp w handles n = w + 4*k, k = 0..99 ; unroll 4 for MLP
    #pragma unroll 1
    for (int k0 = 0; k0 < 100; k0 += 4) {
        int nn[4]; int mk[4]; float2 zv[4], hv[4];
        #pragma unroll
        for (int j = 0; j < 4; j++) {
            nn[j] = w + 4*(k0 + j);
            mk[j] = s_mask[nn[j]];
            if (mk[j]) {
                zv[j] = zb[((b*OP + nn[j])*MA + m)*32 + lane];
                hv[j] = hb[(b*OP + nn[j])*32 + lane];
            }
        }
        #pragma unroll
        for (int j = 0; j < 4; j++) {
            if (mk[j]) {
                float part = zv[j].x*ve.x + zv[j].y*ve.y;
                #pragma unroll
                for (int o = 16; o; o >>= 1)
                    part += __shfl_xor_sync(0xffffffffu, part, o);
                float e = part + s_sop[nn[j]] + sma;
                e = fmaxf(e, 0.01f*e);              // leaky_relu(0.01)
                float p = __expf(e);                 // no max-sub: |e| small
                denom  += p;
                accz.x += p*zv[j].x; accz.y += p*zv[j].y;
                acch.x += p*hv[j].x; acch.y += p*hv[j].y;
            }
        }
    }

    s_pz[w*F + 2*lane]   = accz.x;
    s_pz[w*F + 2*lane+1] = accz.y;
    s_ph[w*F + 2*lane]   = acch.x;
    s_ph[w*F + 2*lane+1] = acch.y;
    if (lane == 0) s_pd[w] = denom;
    __syncthreads();

    float ah = 0.f, dn = 0.f;
    if (tid < F) {
        const int f = tid;
        float az = s_pz[f] + s_pz[F+f] + s_pz[2*F+f] + s_pz[3*F+f];
        ah       = s_ph[f] + s_ph[F+f] + s_ph[2*F+f] + s_ph[3*F+f];
        dn       = s_pd[0] + s_pd[1] + s_pd[2] + s_pd[3];
        s_accz[f] = az;
    }
    __syncthreads();

    if (tid < F) {
        const int f = tid;
        float val = ah;
        #pragma unroll
        for (int kk = 0; kk < F; kk++)
            val += s_accz[kk] * Wedge[kk*F + f];
        float hbv = g_h[(b*MA + m)*F + f];
        // row_empty (dn==0): h_prime contribution zeroed -> just h
        float hp = (dn > 0.f) ? (val / dn + hbv) : hbv;
        out[(b*MA + m)*F + f] = (hp > 0.f) ? hp : expm1f(hp);   // ELU
    }
}

extern "C" void kernel_launch(void* const* d_in, const int* in_sizes, int n_in,
                              void* d_out, int out_size)
{
    const float* x    = (const float*)d_in[0];
    const float* y    = (const float*)d_in[1];
    const float* z    = (const float*)d_in[2];
    const int*   adj  = (const int*)  d_in[3];
    const float* Wop  = (const float*)d_in[4];
    const float* Wma  = (const float*)d_in[5];
    const float* We   = (const float*)d_in[6];
    const float* att  = (const float*)d_in[7];
    float* out = (float*)d_out;

    prep_kernel<<<NB*OP + NB*MA + 1, F>>>(x, y, Wop, Wma, We, att);
    edge_gat_kernel<<<NB*MA, 128>>>(z, adj, We, out);
}

// round 6
// speedup vs baseline: 1.3432x; 1.3432x over previous
#include <cuda_runtime.h>

#define NB 8
#define OP 400
#define MA 200
#define F 64

// Scratch (allocation-free rule: __device__ globals)
__device__ float g_hop[NB*OP*F];   // h_op = x @ W_op
__device__ float g_sop[NB*OP];     // h_op . a_op
__device__ float g_h  [NB*MA*F];   // h = y @ W_ma
__device__ float g_sma[NB*MA];     // h . a_ma
__device__ float g_vedge[F];       // W_edge @ a_edge

__device__ __forceinline__ float warp_sum(float v) {
    v += __shfl_xor_sync(0xffffffffu, v, 16);
    v += __shfl_xor_sync(0xffffffffu, v, 8);
    v += __shfl_xor_sync(0xffffffffu, v, 4);
    v += __shfl_xor_sync(0xffffffffu, v, 2);
    v += __shfl_xor_sync(0xffffffffu, v, 1);
    return v;
}

// ---------------------------------------------------------------------------
// Prep kernel: small GEMVs.
// ---------------------------------------------------------------------------
__global__ void prep_kernel(const float* __restrict__ x, const float* __restrict__ y,
                            const float* __restrict__ Wop, const float* __restrict__ Wma,
                            const float* __restrict__ Wedge, const float* __restrict__ att)
{
    int blk = blockIdx.x;
    int t = threadIdx.x;

    if (blk == NB*OP + NB*MA) {
        float acc = 0.f;
        #pragma unroll
        for (int f = 0; f < F; f++) acc += Wedge[t*F + f] * att[2*F + f];
        g_vedge[t] = acc;
        return;
    }

    const float* in; const float* W; const float* a;
    float* hout; float* sout;
    if (blk < NB*OP) {
        int row = blk;
        in = x + row*F; W = Wop; a = att;
        hout = g_hop + row*F; sout = g_sop + row;
    } else {
        int row = blk - NB*OP;
        in = y + row*F; W = Wma; a = att + F;
        hout = g_h + row*F; sout = g_sma + row;
    }

    __shared__ float srow[F];
    __shared__ float sred[2];
    srow[t] = in[t];
    __syncthreads();

    float acc = 0.f;
    #pragma unroll
    for (int i = 0; i < F; i++) acc += srow[i] * W[i*F + t];
    hout[t] = acc;

    float v = warp_sum(acc * a[t]);
    if ((t & 31) == 0) sred[t >> 5] = v;
    __syncthreads();
    if (t == 0) sout[0] = sred[0] + sred[1];
}

// ---------------------------------------------------------------------------
// Main kernel: one CTA per (b, m). Masked n's are compacted into a smem index
// list first (warp-uniform trip count!), so the main loop does only useful
// iterations. Each warp handles one n per iteration (float2/lane, 64-wide dot
// via shfl butterfly), unrolled x4 so the 4 independent reduction chains
// overlap. Softmax without max-subtraction (|e| small by construction).
// ---------------------------------------------------------------------------
__global__ __launch_bounds__(128) void edge_gat_kernel(
    const float*  __restrict__ z,
    const int*    __restrict__ adj,
    const float*  __restrict__ Wedge,
    float*        __restrict__ out)
{
    const int bid = blockIdx.x;
    const int b = bid / MA;
    const int m = bid % MA;
    const int tid = threadIdx.x;
    const int w = tid >> 5;
    const int lane = tid & 31;

    __shared__ int   s_cnt;
    __shared__ int   s_idx[OP];    // compacted masked n
    __shared__ float s_sopc[OP];   // compacted sop values
    __shared__ float s_pz[4*F];
    __shared__ float s_ph[4*F];
    __shared__ float s_pd[4];
    __shared__ float s_accz[F];

    if (tid == 0) s_cnt = 0;
    __syncthreads();

    // ballot-compaction of masked n's.
    // NOTE: bound 512 = 4 uniform iterations for ALL threads (527 would give
    // lanes 0-14 an extra iteration -> partial-warp __ballot_sync deadlock).
    for (int i = tid; i < 512; i += 128) {
        int mk = 0;
        float sop = 0.f;
        if (i < OP) {
            mk = adj[(b*OP + i)*MA + m];     // adjT[b,m,i]
            if (mk) sop = g_sop[b*OP + i];
        }
        unsigned ball = __ballot_sync(0xffffffffu, mk != 0);
        int base = 0;
        if (lane == 0 && ball) base = atomicAdd(&s_cnt, __popc(ball));
        base = __shfl_sync(0xffffffffu, base, 0);
        if (mk) {
            int off = base + __popc(ball & ((1u << lane) - 1u));
            s_idx[off]  = i;
            s_sopc[off] = sop;
        }
    }
    const float  sma = g_sma[b*MA + m];
    const float2 ve  = ((const float2*)g_vedge)[lane];
    __syncthreads();
    const int cnt = s_cnt;

    float2 accz = make_float2(0.f, 0.f);
    float2 acch = make_float2(0.f, 0.f);
    float  denom = 0.f;

    const float2* zb = (const float2*)z;
    const float2* hb = (const float2*)g_hop;

    // warp w handles items j = w + 4*it (4-way ILP)
    #pragma unroll 1
    for (int it0 = 0; it0 * 4 + w < cnt; it0 += 4) {
        int    jj[4]; int ok[4]; int nn[4]; float sop[4];
        float2 zv[4], hv[4];
        #pragma unroll
        for (int u = 0; u < 4; u++) {
            jj[u] = (it0 + u) * 4 + w;
            ok[u] = jj[u] < cnt;
            if (ok[u]) {
                nn[u]  = s_idx[jj[u]];
                sop[u] = s_sopc[jj[u]];
                zv[u] = zb[((b*OP + nn[u])*MA + m)*32 + lane];
                hv[u] = hb[(b*OP + nn[u])*32 + lane];
            }
        }
        float dot[4];
        #pragma unroll
        for (int u = 0; u < 4; u++)
            dot[u] = ok[u] ? (zv[u].x*ve.x + zv[u].y*ve.y) : 0.f;
        // four independent butterfly reductions — chains overlap
        #pragma unroll
        for (int o = 16; o; o >>= 1) {
            #pragma unroll
            for (int u = 0; u < 4; u++)
                dot[u] += __shfl_xor_sync(0xffffffffu, dot[u], o);
        }
        #pragma unroll
        for (int u = 0; u < 4; u++) {
            if (ok[u]) {
                float e = dot[u] + sop[u] + sma;
                e = fmaxf(e, 0.01f*e);               // leaky_relu(0.01)
                float p = __expf(e);                 // no max-sub: |e| small
                denom  += p;
                accz.x += p*zv[u].x; accz.y += p*zv[u].y;
                acch.x += p*hv[u].x; acch.y += p*hv[u].y;
            }
        }
    }

    s_pz[w*F + 2*lane]   = accz.x;
    s_pz[w*F + 2*lane+1] = accz.y;
    s_ph[w*F + 2*lane]   = acch.x;
    s_ph[w*F + 2*lane+1] = acch.y;
    if (lane == 0) s_pd[w] = denom;
    __syncthreads();

    float ah = 0.f, dn = 0.f;
    if (tid < F) {
        const int f = tid;
        float az = s_pz[f] + s_pz[F+f] + s_pz[2*F+f] + s_pz[3*F+f];
        ah       = s_ph[f] + s_ph[F+f] + s_ph[2*F+f] + s_ph[3*F+f];
        dn       = s_pd[0] + s_pd[1] + s_pd[2] + s_pd[3];
        s_accz[f] = az;
    }
    __syncthreads();

    if (tid < F) {
        const int f = tid;
        float val = ah;
        #pragma unroll
        for (int kk = 0; kk < F; kk++)
            val += s_accz[kk] * Wedge[kk*F + f];
        float hbv = g_h[(b*MA + m)*F + f];
        // row_empty (dn==0): h_prime contribution zeroed -> just h
        float hp = (dn > 0.f) ? (val / dn + hbv) : hbv;
        out[(b*MA + m)*F + f] = (hp > 0.f) ? hp : expm1f(hp);   // ELU
    }
}

extern "C" void kernel_launch(void* const* d_in, const int* in_sizes, int n_in,
                              void* d_out, int out_size)
{
    const float* x    = (const float*)d_in[0];
    const float* y    = (const float*)d_in[1];
    const float* z    = (const float*)d_in[2];
    const int*   adj  = (const int*)  d_in[3];
    const float* Wop  = (const float*)d_in[4];
    const float* Wma  = (const float*)d_in[5];
    const float* We   = (const float*)d_in[6];
    const float* att  = (const float*)d_in[7];
    float* out = (float*)d_out;

    prep_kernel<<<NB*OP + NB*MA + 1, F>>>(x, y, Wop, Wma, We, att);
    edge_gat_kernel<<<NB*MA, 128>>>(z, adj, We, out);
}